// round 4
// baseline (speedup 1.0000x reference)
#include <cuda_runtime.h>
#include <math.h>

typedef unsigned long long u64;

#define NIMG 16
#define NO   192
#define Hh   160
#define Wd   160
#define HW   25600
#define XPAD 68

#define KHKW3 2916
#define P3    9
#define A3    26244
#define B3    186624
#define U3IMG 1679616
#define KHKW5 1024
#define P5    25
#define A5    25600
#define U5IMG 1638400
#define NPI   560

// ---------------- scratch ----------------
__device__ __align__(16) float g_ex[(size_t)NIMG*NO*HW];
__device__ __align__(16) float g_u3[(size_t)NIMG*U3IMG];
__device__ __align__(16) float g_u5[(size_t)NIMG*U5IMG];
__device__ __align__(16) float g_sf1[NIMG*HW];
__device__ __align__(16) float g_sf3[NIMG*P3*KHKW3];
__device__ __align__(16) float g_sf5[NIMG*P5*KHKW5];
__device__ float g_Z[NPI], g_S[NPI*64], g_Pm[NPI*64];
__device__ float g_gt[NPI*64], g_veff[NPI*64], g_beff[NPI];
__device__ __align__(16) float g_Wall[256*64];   // rows 0..191: fus@res (k,o); 192..255: fus^T (c,o)
__device__ float g_vb[64];
__device__ __align__(16) float g_expWt[64*NO];   // [c][o]

// ---------------- helpers ----------------
__device__ __forceinline__ u64 pk2(float lo, float hi){
    u64 r; asm("mov.b64 %0,{%1,%2};":"=l"(r):"f"(lo),"f"(hi)); return r;
}
__device__ __forceinline__ void fma2(u64 &d, u64 a, u64 b){
    asm("fma.rn.f32x2 %0,%1,%2,%3;":"=l"(d):"l"(a),"l"(b),"l"(d));
}
__device__ __forceinline__ float2 up2(u64 v){
    float2 f; asm("mov.b64 {%0,%1},%2;":"=f"(f.x),"=f"(f.y):"l"(v)); return f;
}
__device__ __forceinline__ float sigf(float x){ return 1.f/(1.f+expf(-x)); }
__device__ __forceinline__ int cover3(int h, int* r){
    int n=0;
    #pragma unroll
    for(int i=0;i<3;i++){ int lo=53*i; if(h>=lo && h<=lo+53) r[n++]=i; }
    return n;
}

// ================ K0a: zero accumulators ================
__global__ void k_zero(){
    int i = blockIdx.x*256 + threadIdx.x;
    if(i < NPI) g_Z[i]=0.f;
    if(i < NPI*64){ g_S[i]=0.f; g_Pm[i]=0.f; }
}

// ================ K0b: weight prep ================
__global__ void k_wprep(const float* __restrict__ exp_w, const float* __restrict__ res_w,
                        const float* __restrict__ res_b, const float* __restrict__ fus_w,
                        const float* __restrict__ fus_b){
    int t = threadIdx.x;
    for(int i=t;i<64*NO;i+=256){ int c=i/NO, o=i%NO; g_expWt[i]=exp_w[o*64+c]; }
    for(int i=t;i<NO*64;i+=256){
        int k=i/64, o=i%64; float s=0.f;
        for(int c=0;c<64;c++) s += fus_w[o*64+c]*res_w[c*NO+k];
        g_Wall[i]=s;
    }
    for(int i=t;i<64*64;i+=256){ int c=i/64, o=i%64; g_Wall[(192+c)*64+o]=fus_w[o*64+c]; }
    for(int o=t;o<64;o+=256){
        float s=fus_b[o];
        for(int c=0;c<64;c++) s += fus_w[o*64+c]*res_b[c];
        g_vb[o]=s;
    }
}

// ================ K1: ex = Wexp @ x  (register-tiled 6ob x 8px) ================
__global__ void __launch_bounds__(256) k1(const float* __restrict__ x,
                                          const float* __restrict__ exp_b){
    __shared__ __align__(16) float xs[64*XPAD];
    int t = threadIdx.x;
    int wt = blockIdx.x, hb = blockIdx.y, n = blockIdx.z;
    int w0 = wt*32, h0 = hb*2;

    const float* xp = x + (size_t)n*64*HW + (size_t)h0*Wd + w0;
    for(int i=t;i<1024;i+=256){
        int c=i>>4, q=(i&15)*4, r=q>>5, col=q&31;
        *(float4*)&xs[c*XPAD+q] = *(const float4*)&xp[(size_t)c*HW + r*Wd + col];
    }
    __syncthreads();

    int pxg = t&7, obg = t>>3;
    int pb = pxg*8, ob0 = obg*6;

    u64 acc[6][4];
    #pragma unroll
    for(int a=0;a<6;a++)
        #pragma unroll
        for(int j=0;j<4;j++) acc[a][j]=0ull;

    for(int c=0;c<64;c++){
        u64 xv[4];
        #pragma unroll
        for(int j=0;j<4;j++) xv[j]=*(const u64*)&xs[c*XPAD+pb+j*2];
        const float2* wr = (const float2*)&g_expWt[c*NO + ob0];
        float2 wA=__ldg(&wr[0]), wB=__ldg(&wr[1]), wC=__ldg(&wr[2]);
        float wv[6] = {wA.x,wA.y,wB.x,wB.y,wC.x,wC.y};
        #pragma unroll
        for(int a=0;a<6;a++){
            u64 wp = pk2(wv[a],wv[a]);
            #pragma unroll
            for(int j=0;j<4;j++) fma2(acc[a][j], wp, xv[j]);
        }
    }

    int r = pb>>5, colb = pb&31;
    float* exg = g_ex + (size_t)n*NO*HW + (size_t)(h0+r)*Wd + w0 + colb;
    #pragma unroll
    for(int a=0;a<6;a++){
        float b = __ldg(&exp_b[ob0+a]);
        float2 v0=up2(acc[a][0]), v1=up2(acc[a][1]), v2=up2(acc[a][2]), v3=up2(acc[a][3]);
        float4 f0 = make_float4(v0.x+b, v0.y+b, v1.x+b, v1.y+b);
        float4 f1 = make_float4(v2.x+b, v2.y+b, v3.x+b, v3.y+b);
        *(float4*)&exg[(size_t)(ob0+a)*HW    ] = f0;
        *(float4*)&exg[(size_t)(ob0+a)*HW + 4] = f1;
    }
}

// ================ K2: repack into unfold order (warp-per-ci) ================
__global__ void __launch_bounds__(256) k2_5(){
    __shared__ __align__(16) float rb[8][800];
    int y = blockIdx.x, n = blockIdx.y;
    int wp = threadIdx.x >> 5, lane = threadIdx.x & 31;
    for(int cit=0; cit<8; cit++){
        int ci = cit*8 + wp;
        const float* src = g_ex + (size_t)n*NO*HW + (size_t)(128+ci)*HW;
        #pragma unroll
        for(int ph=0; ph<5; ph++){
            const float* row = src + (size_t)(ph*32+y)*Wd;
            #pragma unroll
            for(int it=0; it<5; it++){
                int w = lane + it*32;
                rb[wp][lane*25 + ph*5 + it] = row[w];
            }
        }
        __syncwarp();
        float4* dst = (float4*)(g_u5 + (size_t)n*U5IMG + (size_t)(ci*1024 + y*32)*25);
        const float4* srb = (const float4*)rb[wp];
        #pragma unroll
        for(int it=0; it<7; it++){
            int k = lane + it*32;
            if(k < 200) dst[k] = srb[k];
        }
        __syncwarp();
    }
}
__global__ void __launch_bounds__(256) k2_3(){
    __shared__ __align__(16) float rb[8][486];
    int yy = blockIdx.x, n = blockIdx.y;
    int wp = threadIdx.x >> 5, lane = threadIdx.x & 31;
    for(int cit=0; cit<8; cit++){
        int ci = cit*8 + wp;
        const float* src = g_ex + (size_t)n*NO*HW + (size_t)(64+ci)*HW;
        #pragma unroll
        for(int ph=0; ph<3; ph++){
            const float* row = src + (size_t)(53*ph+yy)*Wd;
            #pragma unroll
            for(int it=0; it<5; it++){
                int w = lane + it*32;
                float v = row[w];
                #pragma unroll
                for(int pw=0; pw<3; pw++){
                    int xx = w - 53*pw;
                    if(xx>=0 && xx<54) rb[wp][xx*9 + ph*3 + pw] = v;
                }
            }
        }
        __syncwarp();
        float2* dst = (float2*)(g_u3 + (size_t)n*U3IMG + (size_t)ci*A3 + (size_t)yy*486);
        const float2* srb = (const float2*)rb[wp];
        #pragma unroll
        for(int it=0; it<8; it++){
            int k = lane + it*32;
            if(k < 243) dst[k] = srb[k];
        }
        __syncwarp();
    }
}

// ================ K3: pseudo-image stats (Z, S, Pm), q-tile = 128 ================
__global__ void __launch_bounds__(256) k_stats(const float* __restrict__ ub, int khkw,
                                               size_t imgstride, int piBase,
                                               const float* __restrict__ wq,
                                               const float* __restrict__ wqb){
    __shared__ float Vs[64*129];
    __shared__ float part[2*128];
    __shared__ float es[128];
    int q0 = blockIdx.x*128, bp = blockIdx.y, n = blockIdx.z;
    int t = threadIdx.x;
    const float* base = ub + (size_t)n*imgstride + (size_t)bp*64*khkw + q0;
    int qlim = khkw - q0; if(qlim>128) qlim=128;

    for(int i=t;i<2048;i+=256){
        int c=i>>5, j4=(i&31)*4;
        float4 v = (j4<qlim) ? *(const float4*)&base[(size_t)c*khkw + j4]
                             : make_float4(0.f,0.f,0.f,0.f);
        float* vp = &Vs[c*129+j4];
        vp[0]=v.x; vp[1]=v.y; vp[2]=v.z; vp[3]=v.w;
    }
    __syncthreads();
    {
        int j=t&127, cg=t>>7;
        float s=0.f;
        #pragma unroll 8
        for(int cc=cg*32; cc<cg*32+32; cc++) s += wq[cc]*Vs[cc*129+j];
        part[cg*128+j]=s;
    }
    __syncthreads();
    int pi = piBase + n*gridDim.y + bp;
    if(t<128){
        float qd = part[t]+part[128+t] + wqb[0];
        float e = (t<qlim) ? expf(qd) : 0.f;
        es[t]=e;
        float z=e;
        for(int off=16;off;off>>=1) z += __shfl_xor_sync(0xffffffffu,z,off);
        if((t&31)==0) atomicAdd(&g_Z[pi], z);
    }
    __syncthreads();
    {
        int c=t&63, jg=t>>6;
        float ss=0.f, pm=0.f;
        #pragma unroll 8
        for(int jj=jg*32; jj<jg*32+32; jj++){ float v=Vs[c*129+jj]; ss += v*es[jj]; pm += v; }
        atomicAdd(&g_S[pi*64+c], ss);
        atomicAdd(&g_Pm[pi*64+c], pm);
    }
}

// ================ K4: per-pseudo-image finalize ================
__global__ void __launch_bounds__(64) k4(const float* __restrict__ chwv_w, const float* __restrict__ chwv_b,
                                         const float* __restrict__ chwz_w, const float* __restrict__ chwz_b,
                                         const float* __restrict__ ln_g,  const float* __restrict__ ln_b,
                                         const float* __restrict__ spwq_w,const float* __restrict__ spwq_b,
                                         const float* __restrict__ spwv_w,const float* __restrict__ spwv_b){
    int p = blockIdx.x, t = threadIdx.x;
    float hw = (p<16) ? 25600.f : ((p<160) ? 2916.f : 1024.f);
    __shared__ float xbar[64], pmean[64], wz[32], red[64], swq[32];

    float Zinv = 1.f/g_Z[p];
    xbar[t]  = g_S[p*64+t]*Zinv;
    pmean[t] = g_Pm[p*64+t]/hw;
    __syncthreads();

    if(t<32){
        float s = chwv_b[t];
        for(int c=0;c<64;c++) s += chwv_w[t*64+c]*xbar[c];
        wz[t]=s;
    }
    __syncthreads();

    float z = chwz_b[t];
    for(int j=0;j<32;j++) z += chwz_w[t*32+j]*wz[j];

    red[t]=z; __syncthreads();
    for(int s=32;s>0;s>>=1){ if(t<s) red[t]+=red[t+s]; __syncthreads(); }
    float mu = red[0]*(1.f/64.f); __syncthreads();
    float d = z-mu;
    red[t]=d*d; __syncthreads();
    for(int s=32;s>0;s>>=1){ if(t<s) red[t]+=red[t+s]; __syncthreads(); }
    float var = red[0]*(1.f/64.f);

    float zn = d*rsqrtf(var+1e-5f)*ln_g[t] + ln_b[t];
    g_gt[p*64+t] = sigf(zn);
    __syncthreads();

    if(t<32){
        float s = spwq_b[t];
        for(int c=0;c<64;c++) s += spwq_w[t*64+c]*pmean[c];
        float m=s;
        for(int off=16;off;off>>=1) m=fmaxf(m,__shfl_xor_sync(0xffffffffu,m,off));
        float e=expf(s-m), sum=e;
        for(int off=16;off;off>>=1) sum+=__shfl_xor_sync(0xffffffffu,sum,off);
        swq[t]=e/sum;
    }
    __syncthreads();

    float v=0.f;
    for(int j=0;j<32;j++) v += swq[j]*spwv_w[j*64+t];
    g_veff[p*64+t]=v;
    if(t==0){
        float b=0.f;
        for(int j=0;j<32;j++) b += swq[j]*spwv_b[j];
        g_beff[p]=b;
    }
}

// ================ K5: s-field, q-tile = 128 ================
__global__ void __launch_bounds__(256) k_sfield(const float* __restrict__ ub, int khkw,
                                                size_t imgstride, int piBase,
                                                float* __restrict__ sf){
    __shared__ float Vs[64*129];
    __shared__ float part[2*128];
    __shared__ float ve[64];
    int q0 = blockIdx.x*128, bp = blockIdx.y, n = blockIdx.z;
    int t = threadIdx.x;
    int pi = piBase + n*gridDim.y + bp;
    const float* base = ub + (size_t)n*imgstride + (size_t)bp*64*khkw + q0;
    int qlim = khkw - q0; if(qlim>128) qlim=128;

    if(t<64) ve[t]=g_veff[pi*64+t];
    for(int i=t;i<2048;i+=256){
        int c=i>>5, j4=(i&31)*4;
        float4 v = (j4<qlim) ? *(const float4*)&base[(size_t)c*khkw + j4]
                             : make_float4(0.f,0.f,0.f,0.f);
        float* vp = &Vs[c*129+j4];
        vp[0]=v.x; vp[1]=v.y; vp[2]=v.z; vp[3]=v.w;
    }
    __syncthreads();
    {
        int j=t&127, cg=t>>7;
        float s=0.f;
        #pragma unroll 8
        for(int cc=cg*32; cc<cg*32+32; cc++) s += ve[cc]*Vs[cc*129+j];
        part[cg*128+j]=s;
    }
    __syncthreads();
    if(t<128 && t<qlim){
        float sd = part[t]+part[128+t] + g_beff[pi];
        sf[(size_t)n*(gridDim.y*khkw) + (size_t)bp*khkw + q0 + t] = sigf(sd);
    }
}

// ================ K6: multiplier + fused output GEMM (8ob x 8px, split-k 4) ================
__global__ void __launch_bounds__(256) k6(const float* __restrict__ x, float* __restrict__ out){
    __shared__ __align__(16) float vs[256*XPAD];   // rows 0..191 ex', 192..255 x; reused for reduction
    __shared__ int ncS[32], C0S[32], C1S[32];
    __shared__ int nrS[2], R0S[2], R1S[2];

    int t = threadIdx.x;
    int wt = blockIdx.x, hb = blockIdx.y, n = blockIdx.z;
    int w0 = wt*32, h0 = hb*2;

    const float* exg = g_ex + (size_t)n*NO*HW + (size_t)h0*Wd + w0;
    for(int i=t;i<3072;i+=256){
        int k=i>>4, q=(i&15)*4, r=q>>5, col=q&31;
        *(float4*)&vs[k*XPAD+q] = *(const float4*)&exg[(size_t)k*HW + r*Wd + col];
    }
    const float* xp = x + (size_t)n*64*HW + (size_t)h0*Wd + w0;
    for(int i=t;i<1024;i+=256){
        int c=i>>4, q=(i&15)*4, r=q>>5, col=q&31;
        *(float4*)&vs[(192+c)*XPAD+q] = *(const float4*)&xp[(size_t)c*HW + r*Wd + col];
    }
    if(t<2){ int R[2]; int nr=cover3(h0+t,R); nrS[t]=nr; R0S[t]=R[0]; R1S[t]=(nr>1)?R[1]:R[0]; }
    if(t<32){ int C[2]; int nc=cover3(w0+t,C); ncS[t]=nc; C0S[t]=C[0]; C1S[t]=(nc>1)?C[1]:C[0]; }
    __syncthreads();

    // multiplier on ex rows
    for(int i=t;i<12288;i+=256){
        int k=i>>6, px=i&63, rr=px>>5, col=px&31;
        int h=h0+rr, w=w0+col;
        int win=k>>6, ci=k&63;
        float m;
        if(win==0){
            m = g_gt[n*64+ci] + g_sf1[n*HW + h*Wd + w];
        } else if(win==2){
            int p = (h>>5)*5 + (w>>5);
            int r5 = (h&31)*32 + (w&31);
            int G = ci*A5 + r5*P5 + p;
            int bp = G>>16, mm = G&65535, cp = mm>>10, q = mm&1023;
            int pi = 160 + n*25 + bp;
            m = g_gt[pi*64+cp] + g_sf5[n*25600 + bp*1024 + q];
        } else {
            m = 0.f;
            int nr = nrS[rr], nc = ncS[col];
            #pragma unroll
            for(int ri=0;ri<2;ri++){
                if(ri>=nr) break;
                int ph = (ri==0)?R0S[rr]:R1S[rr];
                #pragma unroll
                for(int cj=0;cj<2;cj++){
                    if(cj>=nc) break;
                    int pw = (cj==0)?C0S[col]:C1S[col];
                    int p = ph*3+pw;
                    int r3 = (h-53*ph)*54 + (w-53*pw);
                    int G = ci*A3 + r3*P3 + p;
                    int bp = G/B3, mm = G - bp*B3;
                    int cp = mm/KHKW3, q = mm - cp*KHKW3;
                    int pi = 16 + n*9 + bp;
                    m += g_gt[pi*64+cp] + g_sf3[n*26244 + bp*KHKW3 + q];
                }
            }
            m *= 1.f/(float)(nr*nc);
        }
        vs[k*XPAD+px] *= (1.f + m);
    }
    __syncthreads();

    // GEMM: out[64ob][64px] = Wall[256k][64ob]^T @ vs[256k][64px]
    int pxg = t&7, obg = (t>>3)&7, ks = t>>6;
    int pb = pxg*8, ob0 = obg*8;

    u64 acc[8][4];
    #pragma unroll
    for(int a=0;a<8;a++)
        #pragma unroll
        for(int j=0;j<4;j++) acc[a][j]=0ull;

    int kbase = ks*64;
    for(int kk=0;kk<64;kk++){
        int k = kbase + kk;
        u64 dv[4];
        #pragma unroll
        for(int j=0;j<4;j++) dv[j]=*(const u64*)&vs[k*XPAD+pb+j*2];
        const float4* wr = (const float4*)&g_Wall[k*64 + ob0];
        float4 wA=__ldg(&wr[0]), wB=__ldg(&wr[1]);
        float wv[8] = {wA.x,wA.y,wA.z,wA.w,wB.x,wB.y,wB.z,wB.w};
        #pragma unroll
        for(int a=0;a<8;a++){
            u64 wp = pk2(wv[a],wv[a]);
            #pragma unroll
            for(int j=0;j<4;j++) fma2(acc[a][j], wp, dv[j]);
        }
    }
    __syncthreads();

    // stage partials: red[ks][ob][px] at stride 68
    #pragma unroll
    for(int a=0;a<8;a++){
        int ob = ob0 + a;
        float* rp = &vs[(ks*64 + ob)*XPAD + pb];
        #pragma unroll
        for(int j=0;j<4;j++){
            float2 v = up2(acc[a][j]);
            *(float2*)&rp[j*2] = v;
        }
    }
    __syncthreads();

    float* og = out + (size_t)n*64*HW + (size_t)h0*Wd + w0;
    for(int i=t;i<4096;i+=256){
        int ob=i>>6, px=i&63, rr=px>>5, col=px&31;
        float s = vs[(ob)*XPAD+px] + vs[(64+ob)*XPAD+px]
                + vs[(128+ob)*XPAD+px] + vs[(192+ob)*XPAD+px] + g_vb[ob];
        og[(size_t)ob*HW + rr*Wd + col] = s;
    }
}

// ================ launch ================
extern "C" void kernel_launch(void* const* d_in, const int* in_sizes, int n_in,
                              void* d_out, int out_size){
    const float* x      = (const float*)d_in[0];
    const float* exp_w  = (const float*)d_in[1];
    const float* exp_b  = (const float*)d_in[2];
    const float* res_w  = (const float*)d_in[3];
    const float* res_b  = (const float*)d_in[4];
    const float* fus_w  = (const float*)d_in[5];
    const float* fus_b  = (const float*)d_in[6];
    const float* chwv_w = (const float*)d_in[7];
    const float* chwv_b = (const float*)d_in[8];
    const float* chwq_w = (const float*)d_in[9];
    const float* chwq_b = (const float*)d_in[10];
    const float* chwz_w = (const float*)d_in[11];
    const float* chwz_b = (const float*)d_in[12];
    const float* ln_g   = (const float*)d_in[13];
    const float* ln_b   = (const float*)d_in[14];
    const float* spwv_w = (const float*)d_in[15];
    const float* spwv_b = (const float*)d_in[16];
    const float* spwq_w = (const float*)d_in[17];
    const float* spwq_b = (const float*)d_in[18];
    float* out = (float*)d_out;

    float *g_ex_p, *g_u3_p, *g_u5_p;
    float *g_sf1_p, *g_sf3_p, *g_sf5_p;
    cudaGetSymbolAddress((void**)&g_ex_p, g_ex);
    cudaGetSymbolAddress((void**)&g_u3_p, g_u3);
    cudaGetSymbolAddress((void**)&g_u5_p, g_u5);
    cudaGetSymbolAddress((void**)&g_sf1_p, g_sf1);
    cudaGetSymbolAddress((void**)&g_sf3_p, g_sf3);
    cudaGetSymbolAddress((void**)&g_sf5_p, g_sf5);

    k_zero<<<(NPI*64+255)/256, 256>>>();
    k_wprep<<<1, 256>>>(exp_w, res_w, res_b, fus_w, fus_b);

    dim3 grid(Wd/32, Hh/2, NIMG);
    k1<<<grid, 256>>>(x, exp_b);

    k2_5<<<dim3(32,NIMG), 256>>>();
    k2_3<<<dim3(54,NIMG), 256>>>();

    k_stats<<<dim3(200, 1, NIMG), 256>>>(g_ex_p, HW,   (size_t)NO*HW, 0,   chwq_w, chwq_b);
    k_stats<<<dim3(23,  9, NIMG), 256>>>(g_u3_p, KHKW3,(size_t)U3IMG, 16,  chwq_w, chwq_b);
    k_stats<<<dim3(8,  25, NIMG), 256>>>(g_u5_p, KHKW5,(size_t)U5IMG, 160, chwq_w, chwq_b);

    k4<<<NPI, 64>>>(chwv_w, chwv_b, chwz_w, chwz_b, ln_g, ln_b,
                    spwq_w, spwq_b, spwv_w, spwv_b);

    k_sfield<<<dim3(200, 1, NIMG), 256>>>(g_ex_p, HW,   (size_t)NO*HW, 0,   g_sf1_p);
    k_sfield<<<dim3(23,  9, NIMG), 256>>>(g_u3_p, KHKW3,(size_t)U3IMG, 16,  g_sf3_p);
    k_sfield<<<dim3(8,  25, NIMG), 256>>>(g_u5_p, KHKW5,(size_t)U5IMG, 160, g_sf5_p);

    k6<<<grid, 256>>>(x, out);
}

// round 5
// speedup vs baseline: 1.2622x; 1.2622x over previous
#include <cuda_runtime.h>
#include <cuda_fp16.h>
#include <math.h>

typedef unsigned long long u64;

#define NIMG 16
#define NO   192
#define Hh   160
#define Wd   160
#define HW   25600
#define PAD  36

#define KHKW3 2916
#define P3    9
#define A3    26244
#define B3    186624
#define U3IMG 1679616
#define KHKW5 1024
#define P5    25
#define A5    25600
#define U5IMG 1638400
#define NPI   560

// ---------------- scratch ----------------
__device__ __align__(16) __half g_ex[(size_t)NIMG*NO*HW];
__device__ __align__(16) __half g_u3[(size_t)NIMG*U3IMG];
__device__ __align__(16) __half g_u5[(size_t)NIMG*U5IMG];
__device__ __align__(16) float g_sf1[NIMG*HW];
__device__ __align__(16) float g_sf3[NIMG*P3*KHKW3];
__device__ __align__(16) float g_sf5[NIMG*P5*KHKW5];
__device__ float g_Z[NPI], g_S[NPI*64], g_Pm[NPI*64];
__device__ float g_gt[NPI*64], g_veff[NPI*64], g_beff[NPI];
__device__ __align__(16) float g_W2t[NO*64];
__device__ __align__(16) float g_Ft[64*64];
__device__ float g_vb[64];
__device__ __align__(16) float g_expWt[64*NO];

// ---------------- helpers ----------------
__device__ __forceinline__ u64 pk2(float lo, float hi){
    u64 r; asm("mov.b64 %0,{%1,%2};":"=l"(r):"f"(lo),"f"(hi)); return r;
}
__device__ __forceinline__ void fma2(u64 &d, u64 a, u64 b){
    asm("fma.rn.f32x2 %0,%1,%2,%3;":"=l"(d):"l"(a),"l"(b),"l"(d));
}
__device__ __forceinline__ float2 up2(u64 v){
    float2 f; asm("mov.b64 {%0,%1},%2;":"=f"(f.x),"=f"(f.y):"l"(v)); return f;
}
__device__ __forceinline__ float sigf(float x){ return 1.f/(1.f+expf(-x)); }
__device__ __forceinline__ int cover3(int h, int* r){
    int n=0;
    #pragma unroll
    for(int i=0;i<3;i++){ int lo=53*i; if(h>=lo && h<=lo+53) r[n++]=i; }
    return n;
}

// ================ K0a: zero accumulators ================
__global__ void k_zero(){
    int i = blockIdx.x*256 + threadIdx.x;
    if(i < NPI) g_Z[i]=0.f;
    if(i < NPI*64){ g_S[i]=0.f; g_Pm[i]=0.f; }
}

// ================ K0b: weight prep ================
__global__ void k_wprep(const float* __restrict__ exp_w, const float* __restrict__ res_w,
                        const float* __restrict__ res_b, const float* __restrict__ fus_w,
                        const float* __restrict__ fus_b){
    int t = threadIdx.x;
    for(int i=t;i<64*NO;i+=256){ int c=i/NO, o=i%NO; g_expWt[i]=exp_w[o*64+c]; }
    for(int i=t;i<64*64;i+=256){ int c=i/64, o=i%64; g_Ft[i]=fus_w[o*64+c]; }
    for(int i=t;i<NO*64;i+=256){
        int k=i/64, o=i%64; float s=0.f;
        for(int c=0;c<64;c++) s += fus_w[o*64+c]*res_w[c*NO+k];
        g_W2t[i]=s;
    }
    for(int o=t;o<64;o+=256){
        float s=fus_b[o];
        for(int c=0;c<64;c++) s += fus_w[o*64+c]*res_b[c];
        g_vb[o]=s;
    }
}

// ================ K1: ex = Wexp @ x (R3 structure, fp16 output) ================
__global__ void __launch_bounds__(256) k1(const float* __restrict__ x,
                                          const float* __restrict__ exp_b){
    __shared__ __align__(16) float xs[64*PAD];
    int t = threadIdx.x;
    int wt = blockIdx.x, h = blockIdx.y, n = blockIdx.z;
    int w0 = wt*32;

    const float* xp = x + (size_t)n*64*HW + (size_t)h*Wd + w0;
    for(int i=t;i<512;i+=256){
        int c=i>>3, grp=(i&7)*4;
        *(float4*)&xs[c*PAD+grp] = *(const float4*)&xp[(size_t)c*HW+grp];
    }
    __syncthreads();

    int ob = t&63, pg = t>>6, pb = pg*8;
    u64 acc[3][4];
    #pragma unroll
    for(int a=0;a<3;a++)
        #pragma unroll
        for(int j=0;j<4;j++) acc[a][j]=0ull;
    for(int c=0;c<64;c++){
        u64 xv[4];
        #pragma unroll
        for(int j=0;j<4;j++) xv[j]=*(const u64*)&xs[c*PAD+pb+j*2];
        #pragma unroll
        for(int a=0;a<3;a++){
            float w = g_expWt[c*NO + ob + a*64];
            u64 wp = pk2(w,w);
            #pragma unroll
            for(int j=0;j<4;j++) fma2(acc[a][j], wp, xv[j]);
        }
    }
    __half* exg = g_ex + (size_t)n*NO*HW + (size_t)h*Wd + w0;
    #pragma unroll
    for(int a=0;a<3;a++){
        float b = exp_b[ob+a*64];
        float2 v0=up2(acc[a][0]), v1=up2(acc[a][1]), v2=up2(acc[a][2]), v3=up2(acc[a][3]);
        __half2 h0=__floats2half2_rn(v0.x+b, v0.y+b);
        __half2 h1=__floats2half2_rn(v1.x+b, v1.y+b);
        __half2 h2=__floats2half2_rn(v2.x+b, v2.y+b);
        __half2 h3=__floats2half2_rn(v3.x+b, v3.y+b);
        uint4 pk;
        pk.x=*(unsigned*)&h0; pk.y=*(unsigned*)&h1;
        pk.z=*(unsigned*)&h2; pk.w=*(unsigned*)&h3;
        *(uint4*)&exg[(size_t)(ob+a*64)*HW + pb] = pk;
    }
}

// ================ K2: repack into unfold order (warp-per-ci, fp16) ================
// win5: u5 block for (ci,y) is CONTIGUOUS (800 halves); rb flat layout matches dst flat.
__global__ void __launch_bounds__(256) k2_5(){
    __shared__ __align__(16) __half rb[8][800];
    int y = blockIdx.x, n = blockIdx.y;
    int wp = threadIdx.x >> 5, lane = threadIdx.x & 31;
    for(int cit=0; cit<8; cit++){
        int ci = cit*8 + wp;
        const __half* src = g_ex + (size_t)n*NO*HW + (size_t)(128+ci)*HW;
        #pragma unroll
        for(int ph=0; ph<5; ph++){
            const __half2* row2 = (const __half2*)(src + (size_t)(ph*32+y)*Wd);
            #pragma unroll
            for(int it=0; it<3; it++){
                int idx = lane + it*32;
                if(idx<80){
                    __half2 v = row2[idx];
                    int w = idx*2, pw = w>>5, xx = w&31;
                    rb[wp][xx*25 + ph*5 + pw]     = __low2half(v);
                    rb[wp][(xx+1)*25 + ph*5 + pw] = __high2half(v);
                }
            }
        }
        __syncwarp();
        uint4* dst = (uint4*)(g_u5 + (size_t)n*U5IMG + (size_t)(ci*1024 + y*32)*25);
        const uint4* s = (const uint4*)rb[wp];
        #pragma unroll
        for(int it=0; it<4; it++){
            int k = lane + it*32;
            if(k < 100) dst[k] = s[k];
        }
        __syncwarp();
    }
}
// win3: block for (ci,yy) contiguous (486 halves)
__global__ void __launch_bounds__(256) k2_3(){
    __shared__ __align__(16) __half rb[8][488];
    int yy = blockIdx.x, n = blockIdx.y;
    int wp = threadIdx.x >> 5, lane = threadIdx.x & 31;
    for(int cit=0; cit<8; cit++){
        int ci = cit*8 + wp;
        const __half* src = g_ex + (size_t)n*NO*HW + (size_t)(64+ci)*HW;
        #pragma unroll
        for(int ph=0; ph<3; ph++){
            const __half2* row2 = (const __half2*)(src + (size_t)(53*ph+yy)*Wd);
            #pragma unroll
            for(int it=0; it<3; it++){
                int idx = lane + it*32;
                if(idx<80){
                    __half2 v = row2[idx];
                    int w0_ = idx*2;
                    __half hv[2] = {__low2half(v), __high2half(v)};
                    #pragma unroll
                    for(int hh=0; hh<2; hh++){
                        int w = w0_ + hh;
                        #pragma unroll
                        for(int pw=0; pw<3; pw++){
                            int xx = w - 53*pw;
                            if(xx>=0 && xx<54) rb[wp][xx*9 + ph*3 + pw] = hv[hh];
                        }
                    }
                }
            }
        }
        __syncwarp();
        unsigned* dst = (unsigned*)(g_u3 + (size_t)n*U3IMG + (size_t)ci*A3 + (size_t)yy*486);
        const unsigned* s = (const unsigned*)rb[wp];
        #pragma unroll
        for(int it=0; it<8; it++){
            int k = lane + it*32;
            if(k < 243) dst[k] = s[k];
        }
        __syncwarp();
    }
}

// ================ K3: pseudo-image stats (fp16 input, q-tile 128) ================
__global__ void __launch_bounds__(256) k_stats(const __half* __restrict__ ub, int khkw,
                                               size_t imgstride, int piBase,
                                               const float* __restrict__ wq,
                                               const float* __restrict__ wqb){
    __shared__ float Vs[64*129];
    __shared__ float part[2*128];
    __shared__ float es[128];
    int q0 = blockIdx.x*128, bp = blockIdx.y, n = blockIdx.z;
    int t = threadIdx.x;
    const __half* base = ub + (size_t)n*imgstride + (size_t)bp*64*khkw + q0;
    int qlim = khkw - q0; if(qlim>128) qlim=128;

    for(int i=t;i<4096;i+=256){
        int c=i>>6, j2=(i&63)*2;
        float2 f = make_float2(0.f,0.f);
        if(j2<qlim){
            __half2 v = *(const __half2*)&base[(size_t)c*khkw + j2];
            f = __half22float2(v);
        }
        Vs[c*129+j2]=f.x; Vs[c*129+j2+1]=f.y;
    }
    __syncthreads();
    {
        int j=t&127, cg=t>>7;
        float s=0.f;
        #pragma unroll 8
        for(int cc=cg*32; cc<cg*32+32; cc++) s += wq[cc]*Vs[cc*129+j];
        part[cg*128+j]=s;
    }
    __syncthreads();
    int pi = piBase + n*gridDim.y + bp;
    if(t<128){
        float qd = part[t]+part[128+t] + wqb[0];
        float e = (t<qlim) ? expf(qd) : 0.f;
        es[t]=e;
        float z=e;
        for(int off=16;off;off>>=1) z += __shfl_xor_sync(0xffffffffu,z,off);
        if((t&31)==0) atomicAdd(&g_Z[pi], z);
    }
    __syncthreads();
    {
        int c=t&63, jg=t>>6;
        float ss=0.f, pm=0.f;
        #pragma unroll 8
        for(int jj=jg*32; jj<jg*32+32; jj++){ float v=Vs[c*129+jj]; ss += v*es[jj]; pm += v; }
        atomicAdd(&g_S[pi*64+c], ss);
        atomicAdd(&g_Pm[pi*64+c], pm);
    }
}

// ================ K4: per-pseudo-image finalize ================
__global__ void __launch_bounds__(64) k4(const float* __restrict__ chwv_w, const float* __restrict__ chwv_b,
                                         const float* __restrict__ chwz_w, const float* __restrict__ chwz_b,
                                         const float* __restrict__ ln_g,  const float* __restrict__ ln_b,
                                         const float* __restrict__ spwq_w,const float* __restrict__ spwq_b,
                                         const float* __restrict__ spwv_w,const float* __restrict__ spwv_b){
    int p = blockIdx.x, t = threadIdx.x;
    float hw = (p<16) ? 25600.f : ((p<160) ? 2916.f : 1024.f);
    __shared__ float xbar[64], pmean[64], wz[32], red[64], swq[32];

    float Zinv = 1.f/g_Z[p];
    xbar[t]  = g_S[p*64+t]*Zinv;
    pmean[t] = g_Pm[p*64+t]/hw;
    __syncthreads();

    if(t<32){
        float s = chwv_b[t];
        for(int c=0;c<64;c++) s += chwv_w[t*64+c]*xbar[c];
        wz[t]=s;
    }
    __syncthreads();

    float z = chwz_b[t];
    for(int j=0;j<32;j++) z += chwz_w[t*32+j]*wz[j];

    red[t]=z; __syncthreads();
    for(int s=32;s>0;s>>=1){ if(t<s) red[t]+=red[t+s]; __syncthreads(); }
    float mu = red[0]*(1.f/64.f); __syncthreads();
    float d = z-mu;
    red[t]=d*d; __syncthreads();
    for(int s=32;s>0;s>>=1){ if(t<s) red[t]+=red[t+s]; __syncthreads(); }
    float var = red[0]*(1.f/64.f);

    float zn = d*rsqrtf(var+1e-5f)*ln_g[t] + ln_b[t];
    g_gt[p*64+t] = sigf(zn);
    __syncthreads();

    if(t<32){
        float s = spwq_b[t];
        for(int c=0;c<64;c++) s += spwq_w[t*64+c]*pmean[c];
        float m=s;
        for(int off=16;off;off>>=1) m=fmaxf(m,__shfl_xor_sync(0xffffffffu,m,off));
        float e=expf(s-m), sum=e;
        for(int off=16;off;off>>=1) sum+=__shfl_xor_sync(0xffffffffu,sum,off);
        swq[t]=e/sum;
    }
    __syncthreads();

    float v=0.f;
    for(int j=0;j<32;j++) v += swq[j]*spwv_w[j*64+t];
    g_veff[p*64+t]=v;
    if(t==0){
        float b=0.f;
        for(int j=0;j<32;j++) b += swq[j]*spwv_b[j];
        g_beff[p]=b;
    }
}

// ================ K5: s-field (fp16 input, q-tile 128) ================
__global__ void __launch_bounds__(256) k_sfield(const __half* __restrict__ ub, int khkw,
                                                size_t imgstride, int piBase,
                                                float* __restrict__ sf){
    __shared__ float Vs[64*129];
    __shared__ float part[2*128];
    __shared__ float ve[64];
    int q0 = blockIdx.x*128, bp = blockIdx.y, n = blockIdx.z;
    int t = threadIdx.x;
    int pi = piBase + n*gridDim.y + bp;
    const __half* base = ub + (size_t)n*imgstride + (size_t)bp*64*khkw + q0;
    int qlim = khkw - q0; if(qlim>128) qlim=128;

    if(t<64) ve[t]=g_veff[pi*64+t];
    for(int i=t;i<4096;i+=256){
        int c=i>>6, j2=(i&63)*2;
        float2 f = make_float2(0.f,0.f);
        if(j2<qlim){
            __half2 v = *(const __half2*)&base[(size_t)c*khkw + j2];
            f = __half22float2(v);
        }
        Vs[c*129+j2]=f.x; Vs[c*129+j2+1]=f.y;
    }
    __syncthreads();
    {
        int j=t&127, cg=t>>7;
        float s=0.f;
        #pragma unroll 8
        for(int cc=cg*32; cc<cg*32+32; cc++) s += ve[cc]*Vs[cc*129+j];
        part[cg*128+j]=s;
    }
    __syncthreads();
    if(t<128 && t<qlim){
        float sd = part[t]+part[128+t] + g_beff[pi];
        sf[(size_t)n*(gridDim.y*khkw) + (size_t)bp*khkw + q0 + t] = sigf(sd);
    }
}

// ================ K6: multiplier + fused output GEMM (R3 structure, fp16 ex) ================
__global__ void __launch_bounds__(256) k6(const float* __restrict__ x, float* __restrict__ out){
    __shared__ __align__(16) float exs[NO*PAD];
    __shared__ __align__(16) float xs[64*PAD];
    __shared__ int ncS[32], C0S[32], C1S[32];
    __shared__ int nrS, R0S, R1S;

    int t = threadIdx.x;
    int wt = blockIdx.x, h = blockIdx.y, n = blockIdx.z;
    int w0 = wt*32;

    const __half* exg = g_ex + (size_t)n*NO*HW + (size_t)h*Wd + w0;
    for(int i=t;i<768;i+=256){
        int k=i>>2, q=(i&3)*8;
        uint4 raw = *(const uint4*)&exg[(size_t)k*HW + q];
        __half2* hp = (__half2*)&raw;
        float2 f0=__half22float2(hp[0]), f1=__half22float2(hp[1]);
        float2 f2=__half22float2(hp[2]), f3=__half22float2(hp[3]);
        float* d = &exs[k*PAD+q];
        d[0]=f0.x; d[1]=f0.y; d[2]=f1.x; d[3]=f1.y;
        d[4]=f2.x; d[5]=f2.y; d[6]=f3.x; d[7]=f3.y;
    }
    const float* xp = x + (size_t)n*64*HW + (size_t)h*Wd + w0;
    for(int i=t;i<512;i+=256){
        int c=i>>3, grp=(i&7)*4;
        *(float4*)&xs[c*PAD+grp] = *(const float4*)&xp[(size_t)c*HW+grp];
    }
    if(t==0){ int R[2]; int nr=cover3(h,R); nrS=nr; R0S=R[0]; R1S=(nr>1)?R[1]:R[0]; }
    if(t<32){ int C[2]; int nc=cover3(w0+t,C); ncS[t]=nc; C0S[t]=C[0]; C1S[t]=(nc>1)?C[1]:C[0]; }
    __syncthreads();

    int nr = nrS;
    for(int i=t;i<NO*32;i+=256){
        int k=i>>5, pix=i&31, win=k>>6, ci=k&63;
        int w = w0 + pix;
        float m;
        if(win==0){
            m = g_gt[n*64+ci] + g_sf1[n*HW + h*Wd + w];
        } else if(win==2){
            int p = (h>>5)*5 + (w>>5);
            int r = (h&31)*32 + (w&31);
            int G = ci*A5 + r*P5 + p;
            int bp = G>>16, mm = G&65535, cp = mm>>10, q = mm&1023;
            int pi = 160 + n*25 + bp;
            m = g_gt[pi*64+cp] + g_sf5[n*25600 + bp*1024 + q];
        } else {
            m = 0.f;
            int nc = ncS[pix];
            #pragma unroll
            for(int ri=0;ri<2;ri++){
                if(ri>=nr) break;
                int ph = (ri==0)?R0S:R1S;
                #pragma unroll
                for(int cj=0;cj<2;cj++){
                    if(cj>=nc) break;
                    int pw = (cj==0)?C0S[pix]:C1S[pix];
                    int p = ph*3+pw;
                    int r = (h-53*ph)*54 + (w-53*pw);
                    int G = ci*A3 + r*P3 + p;
                    int bp = G/B3, mm = G - bp*B3;
                    int cp = mm/KHKW3, q = mm - cp*KHKW3;
                    int pi = 16 + n*9 + bp;
                    m += g_gt[pi*64+cp] + g_sf3[n*26244 + bp*KHKW3 + q];
                }
            }
            m *= 1.f/(float)(nr*nc);
        }
        exs[k*PAD+pix] *= (1.f + m);
    }
    __syncthreads();

    int ob = t&63, pg = t>>6, pb = pg*8;
    float vbv = g_vb[ob];
    u64 acc[4];
    #pragma unroll
    for(int j=0;j<4;j++) acc[j]=pk2(vbv,vbv);
    for(int k=0;k<NO;k++){
        float wv = g_W2t[k*64+ob];
        u64 wp = pk2(wv,wv);
        #pragma unroll
        for(int j=0;j<4;j++){ u64 ev=*(const u64*)&exs[k*PAD+pb+j*2]; fma2(acc[j],wp,ev); }
    }
    for(int c=0;c<64;c++){
        float fv = g_Ft[c*64+ob];
        u64 fp = pk2(fv,fv);
        #pragma unroll
        for(int j=0;j<4;j++){ u64 xv=*(const u64*)&xs[c*PAD+pb+j*2]; fma2(acc[j],fp,xv); }
    }
    __syncthreads();
    #pragma unroll
    for(int j=0;j<4;j++){
        float2 v=up2(acc[j]);
        xs[ob*PAD+pb+j*2  ]=v.x;
        xs[ob*PAD+pb+j*2+1]=v.y;
    }
    __syncthreads();
    float* og = out + (size_t)n*64*HW + (size_t)h*Wd + w0;
    for(int i=t;i<512;i+=256){
        int o=i>>3, grp=(i&7)*4;
        *(float4*)&og[(size_t)o*HW+grp] = *(const float4*)&xs[o*PAD+grp];
    }
}

// ================ launch ================
extern "C" void kernel_launch(void* const* d_in, const int* in_sizes, int n_in,
                              void* d_out, int out_size){
    const float* x      = (const float*)d_in[0];
    const float* exp_w  = (const float*)d_in[1];
    const float* exp_b  = (const float*)d_in[2];
    const float* res_w  = (const float*)d_in[3];
    const float* res_b  = (const float*)d_in[4];
    const float* fus_w  = (const float*)d_in[5];
    const float* fus_b  = (const float*)d_in[6];
    const float* chwv_w = (const float*)d_in[7];
    const float* chwv_b = (const float*)d_in[8];
    const float* chwq_w = (const float*)d_in[9];
    const float* chwq_b = (const float*)d_in[10];
    const float* chwz_w = (const float*)d_in[11];
    const float* chwz_b = (const float*)d_in[12];
    const float* ln_g   = (const float*)d_in[13];
    const float* ln_b   = (const float*)d_in[14];
    const float* spwv_w = (const float*)d_in[15];
    const float* spwv_b = (const float*)d_in[16];
    const float* spwq_w = (const float*)d_in[17];
    const float* spwq_b = (const float*)d_in[18];
    float* out = (float*)d_out;

    __half *g_ex_p, *g_u3_p, *g_u5_p;
    float *g_sf1_p, *g_sf3_p, *g_sf5_p;
    cudaGetSymbolAddress((void**)&g_ex_p, g_ex);
    cudaGetSymbolAddress((void**)&g_u3_p, g_u3);
    cudaGetSymbolAddress((void**)&g_u5_p, g_u5);
    cudaGetSymbolAddress((void**)&g_sf1_p, g_sf1);
    cudaGetSymbolAddress((void**)&g_sf3_p, g_sf3);
    cudaGetSymbolAddress((void**)&g_sf5_p, g_sf5);

    k_zero<<<(NPI*64+255)/256, 256>>>();
    k_wprep<<<1, 256>>>(exp_w, res_w, res_b, fus_w, fus_b);

    dim3 grid(Wd/32, Hh, NIMG);
    k1<<<grid, 256>>>(x, exp_b);

    k2_5<<<dim3(32,NIMG), 256>>>();
    k2_3<<<dim3(54,NIMG), 256>>>();

    k_stats<<<dim3(200, 1, NIMG), 256>>>(g_ex_p, HW,   (size_t)NO*HW, 0,   chwq_w, chwq_b);
    k_stats<<<dim3(23,  9, NIMG), 256>>>(g_u3_p, KHKW3,(size_t)U3IMG, 16,  chwq_w, chwq_b);
    k_stats<<<dim3(8,  25, NIMG), 256>>>(g_u5_p, KHKW5,(size_t)U5IMG, 160, chwq_w, chwq_b);

    k4<<<NPI, 64>>>(chwv_w, chwv_b, chwz_w, chwz_b, ln_g, ln_b,
                    spwq_w, spwq_b, spwv_w, spwv_b);

    k_sfield<<<dim3(200, 1, NIMG), 256>>>(g_ex_p, HW,   (size_t)NO*HW, 0,   g_sf1_p);
    k_sfield<<<dim3(23,  9, NIMG), 256>>>(g_u3_p, KHKW3,(size_t)U3IMG, 16,  g_sf3_p);
    k_sfield<<<dim3(8,  25, NIMG), 256>>>(g_u5_p, KHKW5,(size_t)U5IMG, 160, g_sf5_p);

    k6<<<grid, 256>>>(x, out);
}